// round 5
// baseline (speedup 1.0000x reference)
#include <cuda_runtime.h>
#include <cuda_bf16.h>
#include <cstdint>

// Gather: out[g][row][j*32+k] = in[row][g*512 + j*64 + k]
// Work unit: one v8 (8 floats = 32B). Total v8 = 16384*2048/8 = 2^22.
//   v8 flat output index i:
//     g = i>>19, row = (i>>5)&16383, v = i&31, j = v>>2, kq = v&3
//     src (v8 units) = row*512 + g*64 + j*8 + kq
//
// Supply-side fix: dram__cycles_active was only ~73% (DRAM idle 27%) ->
// latency*parallelism shortfall. 256-bit loads carry 8 cache lines per warp
// per instruction (2x the 128-bit path per outstanding-request slot), and
// __launch_bounds__(256,4) gives ptxas enough registers (payload 32 + addr)
// to genuinely front-batch 4 loads per thread before any store.

__global__ void __launch_bounds__(256, 4)
fuse_slice_cat_kernel(const float* __restrict__ in, float* __restrict__ out)
{
    unsigned int i0  = blockIdx.x * 1024u + threadIdx.x;  // v8 index
    unsigned int g   = i0 >> 19;
    unsigned int row = (i0 >> 5) & 16383u;
    unsigned int v   = i0 & 31u;
    unsigned int src = row * 512u + g * 64u + (v >> 2) * 8u + (v & 3u);

    const float* p0 = in  + (size_t)src * 8u;
    float*       q0 = out + (size_t)i0  * 8u;

    float r[4][8];

    // 4 front-batched 256-bit loads; k advances row by 8 -> src by 4096 v8.
    #pragma unroll
    for (int k = 0; k < 4; ++k) {
        const float* p = p0 + (size_t)k * 32768u;   // 8 rows * 4096 floats
        asm volatile(
            "ld.global.v8.f32 {%0,%1,%2,%3,%4,%5,%6,%7}, [%8];"
            : "=f"(r[k][0]), "=f"(r[k][1]), "=f"(r[k][2]), "=f"(r[k][3]),
              "=f"(r[k][4]), "=f"(r[k][5]), "=f"(r[k][6]), "=f"(r[k][7])
            : "l"(p));
    }

    // 4 contiguous 256-bit stores; k advances output by 256 v8 = 2048 floats.
    #pragma unroll
    for (int k = 0; k < 4; ++k) {
        float* q = q0 + (size_t)k * 2048u;
        asm volatile(
            "st.global.v8.f32 [%0], {%1,%2,%3,%4,%5,%6,%7,%8};"
            :: "l"(q),
               "f"(r[k][0]), "f"(r[k][1]), "f"(r[k][2]), "f"(r[k][3]),
               "f"(r[k][4]), "f"(r[k][5]), "f"(r[k][6]), "f"(r[k][7])
            : "memory");
    }
}

extern "C" void kernel_launch(void* const* d_in, const int* in_sizes, int n_in,
                              void* d_out, int out_size)
{
    const float* in  = (const float*)d_in[0];
    float*       out = (float*)d_out;

    // 2^22 v8 units total; 4 per thread, 256 threads/block -> 4096 blocks.
    fuse_slice_cat_kernel<<<4096, 256>>>(in, out);
}

// round 6
// speedup vs baseline: 1.0056x; 1.0056x over previous
#include <cuda_runtime.h>
#include <cuda_bf16.h>
#include <cstdint>

// Gather: out[g][row][j*32+k] = in[row][g*512 + j*64 + k]
//   out flat float4 idx i: g=i>>20, row=(i>>6)&16383, v=i&63
//   src (float4 units) = row*1024 + g*128 + (v>>3)*16 + (v&7)
//
// NEW: block -> (row_tile, group) with GROUP FASTEST (g = bid&7).
// Previously blocks were group-major, so the ~600 concurrently-resident
// blocks all read the same half-dense 128B-used/128B-skipped pattern,
// wasting half of every open DRAM row. With group fastest, the concurrent
// block set covers all 8 groups of the same row band -> their combined read
// stream is a CONTIGUOUS, FULLY DENSE ~37MB sliding window of the input
// (each group reads a different column region of the same rows). DRAM row
// buffers are fully consumed; writes stay 8 independent sequential streams.

__global__ void __launch_bounds__(256)
fuse_slice_cat_kernel(const float4* __restrict__ in, float4* __restrict__ out)
{
    unsigned int b   = blockIdx.x;
    unsigned int g   = b & 7u;        // group: fastest-varying across blocks
    unsigned int t   = b >> 3;        // row tile: 32 rows per block
    unsigned int tid = threadIdx.x;

    // Output base: group g, rows [t*32, t*32+32), 2048 float4 per block.
    unsigned int i0  = (g << 20) + (t << 11) + tid;
    unsigned int row = (t << 5) + (tid >> 6);      // +4 rows per k-step
    unsigned int v   = tid & 63u;
    unsigned int src = row * 1024u + g * 128u + (v >> 3) * 16u + (v & 7u);

    float4 r[8];
    #pragma unroll
    for (int k = 0; k < 8; ++k)
        r[k] = in[src + (unsigned)k * 4096u];      // 4 rows * 1024 f4/row

    #pragma unroll
    for (int k = 0; k < 8; ++k)
        out[i0 + (unsigned)k * 256u] = r[k];
}

extern "C" void kernel_launch(void* const* d_in, const int* in_sizes, int n_in,
                              void* d_out, int out_size)
{
    const float4* in  = (const float4*)d_in[0];
    float4*       out = (float4*)d_out;

    // 2^23 float4 total; 2048 per block -> 4096 blocks (512 row-tiles x 8 groups).
    fuse_slice_cat_kernel<<<4096, 256>>>(in, out);
}

// round 7
// speedup vs baseline: 1.0085x; 1.0028x over previous
#include <cuda_runtime.h>
#include <cuda_bf16.h>
#include <cstdint>

// Gather: out[g][row][j*32+k] = in[row][g*512 + j*64 + k]
//   out flat float4 idx i: g=i>>20, row=(i>>6)&16383, v=i&63
//   src (float4 units) = row*1024 + g*128 + (v>>3)*16 + (v&7)
//
// Verdict from R1-R6: steady state is pinned at ~5.9 TB/s effective
// (268 MB/replay), the structural ceiling for a half-dense-read +
// dense-write stream (hash bit 7 is transparent -> half-density reaches
// every DRAM bank; no reuse exists to exploit). Remaining levers are
// scheduling-granularity only:
//   * 512-thread blocks -> 2048 blocks (half the dispatches), 16 warps/block,
//     2 blocks/SM = full 32-warp occupancy.
//   * group-fastest tile map (best measured occupancy).
//   * proven 8x float4 front-batched body.

__global__ void __launch_bounds__(512)
fuse_slice_cat_kernel(const float4* __restrict__ in, float4* __restrict__ out)
{
    unsigned int b   = blockIdx.x;
    unsigned int g   = b & 7u;          // group fastest across blocks
    unsigned int t   = b >> 3;          // 64-row tile
    unsigned int tid = threadIdx.x;

    // Block covers group g, rows [t*64, t*64+64) -> 4096 float4 of output.
    unsigned int i0  = (g << 20) + (t << 12) + tid;
    unsigned int row = (t << 6) + (tid >> 6);   // +8 rows per k-step
    unsigned int v   = tid & 63u;
    unsigned int src = row * 1024u + g * 128u + (v >> 3) * 16u + (v & 7u);

    float4 r[8];
    #pragma unroll
    for (int k = 0; k < 8; ++k)
        r[k] = in[src + (unsigned)k * 8192u];   // 8 rows * 1024 f4/row

    #pragma unroll
    for (int k = 0; k < 8; ++k)
        out[i0 + (unsigned)k * 512u] = r[k];
}

extern "C" void kernel_launch(void* const* d_in, const int* in_sizes, int n_in,
                              void* d_out, int out_size)
{
    const float4* in  = (const float4*)d_in[0];
    float4*       out = (float4*)d_out;

    // 2^23 float4 total; 4096 per block -> 2048 blocks (256 row-tiles x 8 groups).
    fuse_slice_cat_kernel<<<2048, 512>>>(in, out);
}